// round 1
// baseline (speedup 1.0000x reference)
#include <cuda_runtime.h>
#include <cuda_bf16.h>

#define NB    8192
#define NN    64
#define PITCH 68          // 64 + 4 floats: bank-conflict-free col writes AND row float4 reads
#define SINK_ITERS 20

// sigmoid(gamma) * (1/temp), shared by all 8192 batches
__device__ float d_gs[NN * NN];

__global__ void prep_kernel(const float* __restrict__ gamma) {
    int i = blockIdx.x * blockDim.x + threadIdx.x;
    if (i < NN * NN) {
        float g = gamma[i];
        d_gs[i] = 10.0f / (1.0f + __expf(-g));   // 1/TEMP = 10
    }
}

// One CTA per matrix. Thread c owns column c (64 regs).
// Row reductions go through padded shared memory; col reductions are in-thread.
__global__ __launch_bounds__(64, 8) void sinkhorn_kernel(
    const float* __restrict__ noise, float* __restrict__ out)
{
    __shared__ __align__(16) float tile[NN * PITCH];
    __shared__ __align__(16) float red[NN];

    const int b = blockIdx.x;
    const int c = threadIdx.x;
    const float* np = noise + (size_t)b * (NN * NN);
    float*       op = out   + (size_t)b * (NN * NN);

    // ---- load v = (sigmoid(gamma) + noise) / temp, coalesced ----
    float x[NN];
#pragma unroll
    for (int r = 0; r < NN; r++) {
        x[r] = fmaf(10.0f, __ldg(&np[r * NN + c]), d_gs[r * NN + c]);
    }

    // stage v (column-ordered writes, conflict-free)
#pragma unroll
    for (int r = 0; r < NN; r++) tile[r * PITCH + c] = x[r];
    __syncthreads();

    // ---- per-row max (thread c scans row c with float4, conflict-free) ----
    {
        const float4* rp = reinterpret_cast<const float4*>(&tile[c * PITCH]);
        float4 q = rp[0];
        float m = fmaxf(fmaxf(q.x, q.y), fmaxf(q.z, q.w));
#pragma unroll
        for (int i = 1; i < 16; i++) {
            q = rp[i];
            m = fmaxf(m, fmaxf(fmaxf(q.x, q.y), fmaxf(q.z, q.w)));
        }
        red[c] = m;
    }
    __syncthreads();

    // ---- single exp per element: x = exp(v - rowmax) ----
#pragma unroll
    for (int i = 0; i < 16; i++) {
        float4 m4 = reinterpret_cast<const float4*>(red)[i];
        x[4*i+0] = __expf(x[4*i+0] - m4.x);
        x[4*i+1] = __expf(x[4*i+1] - m4.y);
        x[4*i+2] = __expf(x[4*i+2] - m4.z);
        x[4*i+3] = __expf(x[4*i+3] - m4.w);
    }

    // ---- 20 iters of multiplicative Sinkhorn ----
    float crec = 1.0f;
#pragma unroll 1
    for (int it = 0; it < SINK_ITERS; it++) {
        __syncthreads();                       // prior-iter tile/red readers done
#pragma unroll
        for (int r = 0; r < NN; r++) tile[r * PITCH + c] = x[r];
        __syncthreads();

        // row sums: thread c sums row c (float4, conflict-free)
        {
            const float4* rp = reinterpret_cast<const float4*>(&tile[c * PITCH]);
            float s = 0.0f;
#pragma unroll
            for (int i = 0; i < 16; i++) {
                float4 q = rp[i];
                s += (q.x + q.y) + (q.z + q.w);
            }
            red[c] = __fdividef(1.0f, s);      // rowsum >= 1 (contains exp(0))
        }
        __syncthreads();

        // row-normalize in regs (broadcast float4 reads of reciprocals),
        // accumulate column sum in-thread
        float colsum = 0.0f;
#pragma unroll
        for (int i = 0; i < 16; i++) {
            float4 r4 = reinterpret_cast<const float4*>(red)[i];
            x[4*i+0] *= r4.x; colsum += x[4*i+0];
            x[4*i+1] *= r4.y; colsum += x[4*i+1];
            x[4*i+2] *= r4.z; colsum += x[4*i+2];
            x[4*i+3] *= r4.w; colsum += x[4*i+3];
        }
        crec = __fdividef(1.0f, fmaxf(colsum, 1e-35f));

        if (it < SINK_ITERS - 1) {
#pragma unroll
            for (int r = 0; r < NN; r++) x[r] *= crec;
        }
    }

    // ---- final col-normalize fused with coalesced output write ----
#pragma unroll
    for (int r = 0; r < NN; r++) {
        op[r * NN + c] = x[r] * crec;
    }
}

extern "C" void kernel_launch(void* const* d_in, const int* in_sizes, int n_in,
                              void* d_out, int out_size) {
    const float* gamma = (const float*)d_in[0];   // [64, 64]
    const float* noise = (const float*)d_in[1];   // [8192, 64, 64]
    float* out = (float*)d_out;                   // [8192, 64, 64]

    prep_kernel<<<16, 256>>>(gamma);
    sinkhorn_kernel<<<NB, NN>>>(noise, out);
}

// round 2
// speedup vs baseline: 1.8000x; 1.8000x over previous
#include <cuda_runtime.h>
#include <cuda_bf16.h>

#define NN     64
#define PITCH  68        // 64+4 floats: conflict-free col writes AND 16B-aligned row reads
#define NITERS 20

// sigmoid(gamma) * (1/temp), shared by all 8192 batches
__device__ float d_gs[NN * NN];

__global__ void prep_kernel(const float* __restrict__ gamma) {
    int i = blockIdx.x * blockDim.x + threadIdx.x;
    if (i < NN * NN) {
        d_gs[i] = 10.0f / (1.0f + __expf(-gamma[i]));   // 1/TEMP = 10
    }
}

// Packed dual-fp32 FMA (Blackwell f32x2 pipe: 2 results per instr at scalar-FFMA issue rate)
static __device__ __forceinline__ unsigned long long fma2(
    unsigned long long a, unsigned long long b, unsigned long long c) {
    unsigned long long d;
    asm("fma.rn.f32x2 %0, %1, %2, %3;" : "=l"(d) : "l"(a), "l"(b), "l"(c));
    return d;
}
static __device__ __forceinline__ unsigned long long pack2(float lo, float hi) {
    unsigned long long p;
    asm("mov.b64 %0, {%1, %2};" : "=l"(p) : "f"(lo), "f"(hi));
    return p;
}
static __device__ __forceinline__ float2 unpack2(unsigned long long p) {
    float lo, hi;
    asm("mov.b64 {%0, %1}, %2;" : "=f"(lo), "=f"(hi) : "l"(p));
    return make_float2(lo, hi);
}

// One CTA (64 threads) per matrix. Thread t owns row t AND column t of the
// fixed matrix E = exp(v - rowmax) in packed registers. Each Sinkhorn
// iteration is two register-resident dot products against a broadcast vector:
//   R = 1/(E*C)   (row normalize)     C = 1/(E^T*R)  (col normalize)
__global__ __launch_bounds__(64, 6) void sinkhorn_kernel(
    const float* __restrict__ noise, float* __restrict__ out)
{
    __shared__ __align__(16) float tile[NN * PITCH];
    __shared__ __align__(16) float redM[NN];
    __shared__ __align__(16) float redR[NN];
    __shared__ __align__(16) float redC[NN];

    const int t = threadIdx.x;
    const float* np = noise + (size_t)blockIdx.x * (NN * NN);
    float*       op = out   + (size_t)blockIdx.x * (NN * NN);

    // ---- stage v = 10*(sigmoid(gamma) + noise), column-major writes ----
#pragma unroll
    for (int r = 0; r < NN; r++)
        tile[r * PITCH + t] = fmaf(10.0f, __ldg(&np[r * NN + t]), d_gs[r * NN + t]);
    __syncthreads();

    // ---- per-row max (thread t scans row t, float4, conflict-free) ----
    {
        const float4* rp = (const float4*)&tile[t * PITCH];
        float4 q = rp[0];
        float m = fmaxf(fmaxf(q.x, q.y), fmaxf(q.z, q.w));
#pragma unroll
        for (int i = 1; i < 16; i++) {
            q = rp[i];
            m = fmaxf(m, fmaxf(fmaxf(q.x, q.y), fmaxf(q.z, q.w)));
        }
        redM[t] = m;
        redC[t] = 1.0f;          // initial column scales
    }
    __syncthreads();

    // ---- E column t: exp(v - rowmax), packed pairs; also write back to tile ----
    unsigned long long Ecol[NN / 2];
#pragma unroll
    for (int i = 0; i < 16; i++) {
        float4 m4 = ((const float4*)redM)[i];
        float e0 = __expf(tile[(4 * i + 0) * PITCH + t] - m4.x);
        float e1 = __expf(tile[(4 * i + 1) * PITCH + t] - m4.y);
        float e2 = __expf(tile[(4 * i + 2) * PITCH + t] - m4.z);
        float e3 = __expf(tile[(4 * i + 3) * PITCH + t] - m4.w);
        Ecol[2 * i]     = pack2(e0, e1);
        Ecol[2 * i + 1] = pack2(e2, e3);
        tile[(4 * i + 0) * PITCH + t] = e0;
        tile[(4 * i + 1) * PITCH + t] = e1;
        tile[(4 * i + 2) * PITCH + t] = e2;
        tile[(4 * i + 3) * PITCH + t] = e3;
    }
    __syncthreads();

    // ---- E row t: packed pairs straight from 16B row reads ----
    unsigned long long Erow[NN / 2];
    {
        const ulonglong2* rp = (const ulonglong2*)&tile[t * PITCH];
#pragma unroll
        for (int i = 0; i < 16; i++) {
            ulonglong2 q = rp[i];
            Erow[2 * i]     = q.x;
            Erow[2 * i + 1] = q.y;
        }
    }

    // ---- 20 Sinkhorn iterations: two packed dot products each ----
#pragma unroll 1
    for (int it = 0; it < NITERS; it++) {
        // y[t] = Erow . C  ->  R[t] = 1/y
        unsigned long long a0 = 0ull, a1 = 0ull;
        const ulonglong2* cp = (const ulonglong2*)redC;
#pragma unroll
        for (int i = 0; i < 16; i++) {
            ulonglong2 c2 = cp[i];                 // broadcast, 1 wavefront
            a0 = fma2(Erow[2 * i],     c2.x, a0);
            a1 = fma2(Erow[2 * i + 1], c2.y, a1);
        }
        float2 s0 = unpack2(a0), s1 = unpack2(a1);
        float y = (s0.x + s0.y) + (s1.x + s1.y);
        redR[t] = __fdividef(1.0f, fmaxf(y, 1e-38f));
        __syncthreads();

        // z[t] = Ecol . R  ->  C[t] = 1/z
        a0 = 0ull; a1 = 0ull;
        const ulonglong2* rp = (const ulonglong2*)redR;
#pragma unroll
        for (int i = 0; i < 16; i++) {
            ulonglong2 r2 = rp[i];
            a0 = fma2(Ecol[2 * i],     r2.x, a0);
            a1 = fma2(Ecol[2 * i + 1], r2.y, a1);
        }
        s0 = unpack2(a0); s1 = unpack2(a1);
        float z = (s0.x + s0.y) + (s1.x + s1.y);
        redC[t] = __fdividef(1.0f, fmaxf(z, 1e-38f));
        __syncthreads();
    }

    // ---- output: out[r][t] = E[r][t] * R[r] * C[t], coalesced ----
    const float Ct = redC[t];
#pragma unroll
    for (int i = 0; i < 16; i++) {
        float4 R4 = ((const float4*)redR)[i];
        float2 e0 = unpack2(Ecol[2 * i]);
        float2 e1 = unpack2(Ecol[2 * i + 1]);
        op[(4 * i + 0) * NN + t] = e0.x * R4.x * Ct;
        op[(4 * i + 1) * NN + t] = e0.y * R4.y * Ct;
        op[(4 * i + 2) * NN + t] = e1.x * R4.z * Ct;
        op[(4 * i + 3) * NN + t] = e1.y * R4.w * Ct;
    }
}

extern "C" void kernel_launch(void* const* d_in, const int* in_sizes, int n_in,
                              void* d_out, int out_size) {
    const float* gamma = (const float*)d_in[0];   // [64, 64]
    const float* noise = (const float*)d_in[1];   // [8192, 64, 64]
    float* out = (float*)d_out;                   // [8192, 64, 64]

    prep_kernel<<<16, 256>>>(gamma);
    sinkhorn_kernel<<<8192, NN>>>(noise, out);
}